// round 11
// baseline (speedup 1.0000x reference)
#include <cuda_runtime.h>
#include <cuda_bf16.h>
#include <cuda_fp16.h>
#include <cstdint>

// SDDMM: out[e] = <src_feat[src_idx[e]], dst_feat[dst_idx[e]]>, D=64.
// Phase 1: fp32 -> fp16 table conversion into __device__ scratch.
// Phase 2: warp-cooperative gather. Each warp handles 8 edges per pass:
//   - 4 uniform int4 loads broadcast the 16 indices
//   - 16 LDG.32s, each with ALL 32 lanes inside ONE 128B row
//     -> 1 wavefront per LDG at the cross-LDG rate (1.0 cyc/wf) instead of
//        4 within-LDG replay wavefronts (2.07 cyc/wf) of the blocked layout.
//   - hmul2 partials, 9-shfl parity-merge tree reduces all 8 edges.

static constexpr int D = 64;
static constexpr int MAX_NODES = 100000;
static constexpr int THREADS = 256;

// fp16 tables: one row = 64 halves = 128 bytes = 32 x uint (half2).
__device__ __align__(16) __half g_src16[(size_t)MAX_NODES * D];
__device__ __align__(16) __half g_dst16[(size_t)MAX_NODES * D];

union H2U { __half2 h; unsigned u; };

// ---------------- phase 1: fp32 -> fp16 conversion ----------------
__global__ __launch_bounds__(256)
void convert_kernel(const float4* __restrict__ src,
                    const float4* __restrict__ dst,
                    int n_vec4) {               // n_nodes*D/4 per table
    uint2* s16 = reinterpret_cast<uint2*>(g_src16);
    uint2* d16 = reinterpret_cast<uint2*>(g_dst16);
    int stride = gridDim.x * blockDim.x;
    for (int i = blockIdx.x * blockDim.x + threadIdx.x; i < n_vec4; i += stride) {
        float4 a = __ldg(src + i);
        H2U alo, ahi;
        alo.h = __floats2half2_rn(a.x, a.y);
        ahi.h = __floats2half2_rn(a.z, a.w);
        s16[i] = make_uint2(alo.u, ahi.u);

        float4 b = __ldg(dst + i);
        H2U blo, bhi;
        blo.h = __floats2half2_rn(b.x, b.y);
        bhi.h = __floats2half2_rn(b.z, b.w);
        d16[i] = make_uint2(blo.u, bhi.u);
    }
}

// ---------------- phase 2: transposed gather + dot ----------------
__device__ __forceinline__ float edge_partial(unsigned sv, unsigned dv) {
    H2U a, b; a.u = sv; b.u = dv;
    __half2 q = __hmul2(a.h, b.h);
    float2 f = __half22float2(q);
    return f.x + f.y;
}

__global__ __launch_bounds__(THREADS)
void sddmm_dot_t_kernel(const int* __restrict__ src_idx,
                        const int* __restrict__ dst_idx,
                        float* __restrict__ out,
                        int n_edges) {
    const unsigned* S = reinterpret_cast<const unsigned*>(g_src16);  // 32 u32/row
    const unsigned* Dp = reinterpret_cast<const unsigned*>(g_dst16);

    int warp_id = (blockIdx.x * THREADS + threadIdx.x) >> 5;
    int lane = threadIdx.x & 31;
    int e_base = warp_id * 8;
    if (e_base >= n_edges) return;

    int i0, i1, i2, i3, i4, i5, i6, i7;
    int j0, j1, j2, j3, j4, j5, j6, j7;
    if (e_base + 8 <= n_edges) {
        int4 ia = __ldg(reinterpret_cast<const int4*>(src_idx + e_base));
        int4 ib = __ldg(reinterpret_cast<const int4*>(src_idx + e_base + 4));
        int4 ja = __ldg(reinterpret_cast<const int4*>(dst_idx + e_base));
        int4 jb = __ldg(reinterpret_cast<const int4*>(dst_idx + e_base + 4));
        i0 = ia.x; i1 = ia.y; i2 = ia.z; i3 = ia.w;
        i4 = ib.x; i5 = ib.y; i6 = ib.z; i7 = ib.w;
        j0 = ja.x; j1 = ja.y; j2 = ja.z; j3 = ja.w;
        j4 = jb.x; j5 = jb.y; j6 = jb.z; j7 = jb.w;
    } else {
        int last = n_edges - 1;
        int e0 = e_base;
        int ee1 = e_base + 1 <= last ? e_base + 1 : last;
        int ee2 = e_base + 2 <= last ? e_base + 2 : last;
        int ee3 = e_base + 3 <= last ? e_base + 3 : last;
        int ee4 = e_base + 4 <= last ? e_base + 4 : last;
        int ee5 = e_base + 5 <= last ? e_base + 5 : last;
        int ee6 = e_base + 6 <= last ? e_base + 6 : last;
        int ee7 = e_base + 7 <= last ? e_base + 7 : last;
        i0 = __ldg(src_idx + e0);  i1 = __ldg(src_idx + ee1);
        i2 = __ldg(src_idx + ee2); i3 = __ldg(src_idx + ee3);
        i4 = __ldg(src_idx + ee4); i5 = __ldg(src_idx + ee5);
        i6 = __ldg(src_idx + ee6); i7 = __ldg(src_idx + ee7);
        j0 = __ldg(dst_idx + e0);  j1 = __ldg(dst_idx + ee1);
        j2 = __ldg(dst_idx + ee2); j3 = __ldg(dst_idx + ee3);
        j4 = __ldg(dst_idx + ee4); j5 = __ldg(dst_idx + ee5);
        j6 = __ldg(dst_idx + ee6); j7 = __ldg(dst_idx + ee7);
    }

    // 16 single-line loads: each LDG has all 32 lanes inside one 128B row.
    unsigned s0 = __ldg(S + (unsigned)i0 * 32u + lane);
    unsigned s1 = __ldg(S + (unsigned)i1 * 32u + lane);
    unsigned s2 = __ldg(S + (unsigned)i2 * 32u + lane);
    unsigned s3 = __ldg(S + (unsigned)i3 * 32u + lane);
    unsigned s4 = __ldg(S + (unsigned)i4 * 32u + lane);
    unsigned s5 = __ldg(S + (unsigned)i5 * 32u + lane);
    unsigned s6 = __ldg(S + (unsigned)i6 * 32u + lane);
    unsigned s7 = __ldg(S + (unsigned)i7 * 32u + lane);
    unsigned d0 = __ldg(Dp + (unsigned)j0 * 32u + lane);
    unsigned d1 = __ldg(Dp + (unsigned)j1 * 32u + lane);
    unsigned d2 = __ldg(Dp + (unsigned)j2 * 32u + lane);
    unsigned d3 = __ldg(Dp + (unsigned)j3 * 32u + lane);
    unsigned d4 = __ldg(Dp + (unsigned)j4 * 32u + lane);
    unsigned d5 = __ldg(Dp + (unsigned)j5 * 32u + lane);
    unsigned d6 = __ldg(Dp + (unsigned)j6 * 32u + lane);
    unsigned d7 = __ldg(Dp + (unsigned)j7 * 32u + lane);

    float p0 = edge_partial(s0, d0);
    float p1 = edge_partial(s1, d1);
    float p2 = edge_partial(s2, d2);
    float p3 = edge_partial(s3, d3);
    float p4 = edge_partial(s4, d4);
    float p5 = edge_partial(s5, d5);
    float p6 = edge_partial(s6, d6);
    float p7 = edge_partial(s7, d7);

    // Parity-merge tree: 9 shfls reduce all eight 32-lane sums.
    // Level A (xor16): pairs (p0,p1)(p2,p3)(p4,p5)(p6,p7); bit16 -> edge bit0.
    bool b16 = (lane & 16) != 0;
    float z0 = (b16 ? p1 : p0) + __shfl_xor_sync(0xFFFFFFFFu, b16 ? p0 : p1, 16);
    float z1 = (b16 ? p3 : p2) + __shfl_xor_sync(0xFFFFFFFFu, b16 ? p2 : p3, 16);
    float z2 = (b16 ? p5 : p4) + __shfl_xor_sync(0xFFFFFFFFu, b16 ? p4 : p5, 16);
    float z3 = (b16 ? p7 : p6) + __shfl_xor_sync(0xFFFFFFFFu, b16 ? p6 : p7, 16);
    // Level B (xor8): pairs (z0,z1)(z2,z3); bit8 -> edge bit1.
    bool b8 = (lane & 8) != 0;
    float w0 = (b8 ? z1 : z0) + __shfl_xor_sync(0xFFFFFFFFu, b8 ? z0 : z1, 8);
    float w1 = (b8 ? z3 : z2) + __shfl_xor_sync(0xFFFFFFFFu, b8 ? z2 : z3, 8);
    // Level C (xor4): pair (w0,w1); bit4 -> edge bit2.
    bool b4 = (lane & 4) != 0;
    float v = (b4 ? w1 : w0) + __shfl_xor_sync(0xFFFFFFFFu, b4 ? w0 : w1, 4);
    // Levels D (xor2, xor1): finish.
    v += __shfl_xor_sync(0xFFFFFFFFu, v, 2);
    v += __shfl_xor_sync(0xFFFFFFFFu, v, 1);

    // Lane L (L%4==0) holds edge (bit16 | bit8<<1 | bit4<<2).
    if ((lane & 3) == 0) {
        int eoff = ((lane >> 4) & 1) | (((lane >> 3) & 1) << 1) | (((lane >> 2) & 1) << 2);
        int e = e_base + eoff;
        if (e < n_edges) out[e] = v;
    }
}

extern "C" void kernel_launch(void* const* d_in, const int* in_sizes, int n_in,
                              void* d_out, int out_size) {
    const int*   src_idx  = (const int*)d_in[0];
    const int*   dst_idx  = (const int*)d_in[1];
    const float* src_feat = (const float*)d_in[2];
    const float* dst_feat = (const float*)d_in[3];
    float*       out      = (float*)d_out;

    int n_edges = in_sizes[0];
    int n_feat  = in_sizes[2];          // n_nodes * D
    int n_vec4  = n_feat / 4;

    // Phase 1: convert (grid-stride).
    int cblocks = (n_vec4 + 255) / 256;
    if (cblocks > 1184) cblocks = 1184;
    convert_kernel<<<cblocks, 256>>>(
        reinterpret_cast<const float4*>(src_feat),
        reinterpret_cast<const float4*>(dst_feat),
        n_vec4);

    // Phase 2: 8 edges per warp.
    int n_warps = (n_edges + 7) / 8;
    int gblocks = (n_warps * 32 + THREADS - 1) / THREADS;
    sddmm_dot_t_kernel<<<gblocks, THREADS>>>(src_idx, dst_idx, out, n_edges);
}

// round 13
// speedup vs baseline: 1.2222x; 1.2222x over previous
#include <cuda_runtime.h>
#include <cuda_bf16.h>
#include <cuda_fp16.h>
#include <cstdint>

// SDDMM: out[e] = <src_feat[src_idx[e]], dst_feat[dst_idx[e]]>, D=64.
// Phase 1: fp32 -> fp16 table conversion into __device__ scratch.
// Phase 2: blocked gather (R10 geometry: 8 lanes/edge, 2 edges/thread,
//          4x LDG.128) with fp16-packed math:
//            hfma2 chains (4 ops/edge) -> PRMT pair-merge + hadd2 (3 ops)
//            -> one cvt to float2 -> 3-shfl fp32 parity-merge reduction.

static constexpr int D = 64;
static constexpr int MAX_NODES = 100000;
static constexpr int THREADS = 256;

// fp16 tables: one row = 64 halves = 128 bytes = 8 x uint4.
__device__ __align__(16) __half g_src16[(size_t)MAX_NODES * D];
__device__ __align__(16) __half g_dst16[(size_t)MAX_NODES * D];

union H2U { __half2 h; unsigned u; };

// ---------------- phase 1: fp32 -> fp16 conversion ----------------
__global__ __launch_bounds__(256)
void convert_kernel(const float4* __restrict__ src,
                    const float4* __restrict__ dst,
                    int n_vec4) {               // n_nodes*D/4 per table
    uint2* s16 = reinterpret_cast<uint2*>(g_src16);
    uint2* d16 = reinterpret_cast<uint2*>(g_dst16);
    int stride = gridDim.x * blockDim.x;
    for (int i = blockIdx.x * blockDim.x + threadIdx.x; i < n_vec4; i += stride) {
        float4 a = __ldg(src + i);
        H2U alo, ahi;
        alo.h = __floats2half2_rn(a.x, a.y);
        ahi.h = __floats2half2_rn(a.z, a.w);
        s16[i] = make_uint2(alo.u, ahi.u);

        float4 b = __ldg(dst + i);
        H2U blo, bhi;
        blo.h = __floats2half2_rn(b.x, b.y);
        bhi.h = __floats2half2_rn(b.z, b.w);
        d16[i] = make_uint2(blo.u, bhi.u);
    }
}

// ---------------- phase 2: gather + dot ----------------
// Per-edge hfma2 chain: 4-term fp16 partial per half.
__device__ __forceinline__ __half2 chain8(uint4 a, uint4 b) {
    const __half2* ah = reinterpret_cast<const __half2*>(&a);
    const __half2* bh = reinterpret_cast<const __half2*>(&b);
    __half2 q = __hmul2(ah[0], bh[0]);
    q = __hfma2(ah[1], bh[1], q);
    q = __hfma2(ah[2], bh[2], q);
    q = __hfma2(ah[3], bh[3], q);
    return q;
}

__global__ __launch_bounds__(THREADS)
void sddmm_dot_fp16_kernel(const int* __restrict__ src_idx,
                           const int* __restrict__ dst_idx,
                           float* __restrict__ out,
                           int n_edges) {
    const uint4* sfeat = reinterpret_cast<const uint4*>(g_src16);  // 8 uint4/row
    const uint4* dfeat = reinterpret_cast<const uint4*>(g_dst16);

    int gid  = blockIdx.x * THREADS + threadIdx.x;
    int pair = gid >> 3;            // 2-edge group index
    int lane = gid & 7;

    int n_pairs = (n_edges + 1) >> 1;
    bool live = pair < n_pairs;
    int p = live ? pair : n_pairs - 1;
    int e0 = 2 * p;
    int e1 = e0 + 1;
    int e1c = e1 < n_edges ? e1 : e0;   // clamp odd tail

    int2 iv, jv;
    if (e1 < n_edges) {
        iv = __ldg(reinterpret_cast<const int2*>(src_idx + e0));
        jv = __ldg(reinterpret_cast<const int2*>(dst_idx + e0));
    } else {
        iv.x = __ldg(src_idx + e0); iv.y = __ldg(src_idx + e1c);
        jv.x = __ldg(dst_idx + e0); jv.y = __ldg(dst_idx + e1c);
    }

    // 4 independent 16B loads (one 128B line per row per 8-lane group).
    uint4 s0 = __ldg(sfeat + (unsigned)iv.x * 8u + lane);
    uint4 d0 = __ldg(dfeat + (unsigned)jv.x * 8u + lane);
    uint4 s1 = __ldg(sfeat + (unsigned)iv.y * 8u + lane);
    uint4 d1 = __ldg(dfeat + (unsigned)jv.y * 8u + lane);

    // fp16 chains: q0/q1 hold (4-term, 4-term) partials per edge.
    H2U q0, q1;
    q0.h = chain8(s0, d0);
    q1.h = chain8(s1, d1);

    // PRMT pair-merge: (p0,p1) in one half2, one hadd2 for both edges.
    H2U lo, hi, t;
    lo.u = __byte_perm(q0.u, q1.u, 0x5410);  // (q0.lo, q1.lo)
    hi.u = __byte_perm(q0.u, q1.u, 0x7632);  // (q0.hi, q1.hi)
    t.h = __hadd2(lo.h, hi.h);               // (p0, p1) 8-term sums
    float2 f = __half22float2(t.h);
    float p0 = f.x, p1 = f.y;

    // Parity-merged reduction: 3 shfls reduce both 8-lane sums in fp32.
    bool hi4 = (lane & 4) != 0;
    float send = hi4 ? p0 : p1;
    float keep = hi4 ? p1 : p0;
    float z = keep + __shfl_xor_sync(0xFFFFFFFFu, send, 4);
    z += __shfl_xor_sync(0xFFFFFFFFu, z, 2);
    z += __shfl_xor_sync(0xFFFFFFFFu, z, 1);
    // lane0 -> e0, lane4 -> e1.

    if (live) {
        if (lane == 0) out[e0] = z;
        else if (lane == 4 && e1 < n_edges) out[e1] = z;
    }
}

extern "C" void kernel_launch(void* const* d_in, const int* in_sizes, int n_in,
                              void* d_out, int out_size) {
    const int*   src_idx  = (const int*)d_in[0];
    const int*   dst_idx  = (const int*)d_in[1];
    const float* src_feat = (const float*)d_in[2];
    const float* dst_feat = (const float*)d_in[3];
    float*       out      = (float*)d_out;

    int n_edges = in_sizes[0];
    int n_feat  = in_sizes[2];          // n_nodes * D
    int n_vec4  = n_feat / 4;

    // Phase 1: convert (grid-stride).
    int cblocks = (n_vec4 + 255) / 256;
    if (cblocks > 1184) cblocks = 1184;
    convert_kernel<<<cblocks, 256>>>(
        reinterpret_cast<const float4*>(src_feat),
        reinterpret_cast<const float4*>(dst_feat),
        n_vec4);

    // Phase 2: gather + dot.
    int n_pairs = (n_edges + 1) / 2;
    long long total_threads = (long long)n_pairs * 8;
    int gblocks = (int)((total_threads + THREADS - 1) / THREADS);
    sddmm_dot_fp16_kernel<<<gblocks, THREADS>>>(src_idx, dst_idx, out, n_edges);
}